// round 1
// baseline (speedup 1.0000x reference)
#include <cuda_runtime.h>
#include <cuda_bf16.h>
#include <math.h>

// Problem constants (fixed by setup_inputs)
#define NCH   256
#define OUTP  7
#define NSAMP 14            // OUT * SR
#define NPIX  49            // OUT * OUT

__global__ __launch_bounds__(NCH)
void msroi_kernel(const float* __restrict__ f0,
                  const float* __restrict__ f1,
                  const float* __restrict__ f2,
                  const float* __restrict__ f3,
                  const float* __restrict__ boxes,
                  float* __restrict__ out,
                  int K)
{
    const int k = blockIdx.x;     // roi index
    const int c = threadIdx.x;    // channel

    __shared__ int   s_xl[NSAMP], s_yl[NSAMP];
    __shared__ float s_wx0[NSAMP], s_wx1[NSAMP];
    __shared__ float s_wy0[NSAMP], s_wy1[NSAMP];

    // Every thread computes the (uniform) roi params + level: cheap, broadcast loads.
    const float bx1 = boxes[k * 4 + 0];
    const float by1 = boxes[k * 4 + 1];
    const float bx2 = boxes[k * 4 + 2];
    const float by2 = boxes[k * 4 + 3];

    const float area = fmaxf((bx2 - bx1) * (by2 - by1), 0.0f);
    const float s    = sqrtf(area);
    // lvl = floor(4 + log2(s/224) + 1e-6), clip [2,5], - 2
    float lvlf = floorf(4.0f + log2f(s / 224.0f) + 1e-6f);
    lvlf = fminf(fmaxf(lvlf, 2.0f), 5.0f);
    const int lvl = (int)lvlf - 2;

    const float* feat;
    int H, W;
    float scale;
    if (lvl == 0)      { feat = f0; H = 200; W = 200; scale = 0.25f;    }
    else if (lvl == 1) { feat = f1; H = 100; W = 100; scale = 0.125f;   }
    else if (lvl == 2) { feat = f2; H = 50;  W = 50;  scale = 0.0625f;  }
    else               { feat = f3; H = 25;  W = 25;  scale = 0.03125f; }

    // Precompute the 14 x and 14 y sample positions (shared across channels).
    if (c < NSAMP) {
        const int i  = c;
        const int p  = i >> 1;       // bin index
        const int sub = i & 1;       // subsample index
        const float subofs = ((float)sub + 0.5f) * 0.5f;

        // x axis
        {
            const float x1 = bx1 * scale;
            const float x2 = bx2 * scale;
            const float roi_w = fmaxf(x2 - x1, 1.0f);
            const float bin_w = roi_w * (1.0f / OUTP);
            const float x  = x1 + (float)p * bin_w + subofs * bin_w;
            const float vx = (x >= -1.0f && x <= (float)W) ? 1.0f : 0.0f;
            const float xc = fminf(fmaxf(x, 0.0f), (float)(W - 1));
            const int   xl = (int)fminf(fmaxf(floorf(xc), 0.0f), (float)(W - 2));
            const float lx = xc - (float)xl;
            s_xl[i]  = xl;
            s_wx0[i] = (1.0f - lx) * vx;
            s_wx1[i] = lx * vx;
        }
        // y axis
        {
            const float y1 = by1 * scale;
            const float y2 = by2 * scale;
            const float roi_h = fmaxf(y2 - y1, 1.0f);
            const float bin_h = roi_h * (1.0f / OUTP);
            const float y  = y1 + (float)p * bin_h + subofs * bin_h;
            const float vy = (y >= -1.0f && y <= (float)H) ? 1.0f : 0.0f;
            const float yc = fminf(fmaxf(y, 0.0f), (float)(H - 1));
            const int   yl = (int)fminf(fmaxf(floorf(yc), 0.0f), (float)(H - 2));
            const float ly = yc - (float)yl;
            s_yl[i]  = yl;
            s_wy0[i] = (1.0f - ly) * vy;
            s_wy1[i] = ly * vy;
        }
    }
    __syncthreads();

    const int b = (k >= (K >> 1)) ? 1 : 0;   // batch index (N = K/2 per image)
    const float* __restrict__ base = feat + ((size_t)(b * NCH + c)) * (size_t)(H * W);
    float* __restrict__ op = out + ((size_t)k * NCH + c) * NPIX;

    #pragma unroll
    for (int ph = 0; ph < OUTP; ph++) {
        const int iA = ph * 2, iB = ph * 2 + 1;
        const int   ylA = s_yl[iA],  ylB = s_yl[iB];
        const float wyA0 = s_wy0[iA], wyA1 = s_wy1[iA];
        const float wyB0 = s_wy0[iB], wyB1 = s_wy1[iB];
        const float* rA0 = base + (size_t)ylA * W;
        const float* rA1 = rA0 + W;
        const float* rB0 = base + (size_t)ylB * W;
        const float* rB1 = rB0 + W;

        #pragma unroll
        for (int pw = 0; pw < OUTP; pw++) {
            const int j0 = pw * 2, j1 = pw * 2 + 1;
            const int   xa = s_xl[j0],  xb = s_xl[j1];
            const float wx00 = s_wx0[j0], wx01 = s_wx1[j0];
            const float wx10 = s_wx0[j1], wx11 = s_wx1[j1];

            // sample (iA, j0)
            float gA00 = __ldg(rA0 + xa);
            float gA01 = __ldg(rA0 + xa + 1);
            float gA10 = __ldg(rA1 + xa);
            float gA11 = __ldg(rA1 + xa + 1);
            // sample (iA, j1)
            float gB00 = __ldg(rA0 + xb);
            float gB01 = __ldg(rA0 + xb + 1);
            float gB10 = __ldg(rA1 + xb);
            float gB11 = __ldg(rA1 + xb + 1);
            // sample (iB, j0)
            float gC00 = __ldg(rB0 + xa);
            float gC01 = __ldg(rB0 + xa + 1);
            float gC10 = __ldg(rB1 + xa);
            float gC11 = __ldg(rB1 + xa + 1);
            // sample (iB, j1)
            float gD00 = __ldg(rB0 + xb);
            float gD01 = __ldg(rB0 + xb + 1);
            float gD10 = __ldg(rB1 + xb);
            float gD11 = __ldg(rB1 + xb + 1);

            float acc;
            acc  = wyA0 * (wx00 * gA00 + wx01 * gA01) + wyA1 * (wx00 * gA10 + wx01 * gA11);
            acc += wyA0 * (wx10 * gB00 + wx11 * gB01) + wyA1 * (wx10 * gB10 + wx11 * gB11);
            acc += wyB0 * (wx00 * gC00 + wx01 * gC01) + wyB1 * (wx00 * gC10 + wx01 * gC11);
            acc += wyB0 * (wx10 * gD00 + wx11 * gD01) + wyB1 * (wx10 * gD10 + wx11 * gD11);

            op[ph * OUTP + pw] = acc * 0.25f;
        }
    }
}

extern "C" void kernel_launch(void* const* d_in, const int* in_sizes, int n_in,
                              void* d_out, int out_size)
{
    const float* f0    = (const float*)d_in[0];
    const float* f1    = (const float*)d_in[1];
    const float* f2    = (const float*)d_in[2];
    const float* f3    = (const float*)d_in[3];
    const float* boxes = (const float*)d_in[4];
    const int K = in_sizes[4] / 4;   // 1024 rois

    msroi_kernel<<<K, NCH>>>(f0, f1, f2, f3, boxes, (float*)d_out, K);
}